// round 2
// baseline (speedup 1.0000x reference)
#include <cuda_runtime.h>
#include <math.h>

#define SEQ   2048
#define DIM   4096
#define NH    32
#define NKV   8
#define HD    128
#define KVDIM (NKV * HD)   // 1024
#define NREP  (NH / NKV)   // 4

// Scratch (device globals: allocation-free rule)
__device__ float g_q[SEQ * DIM];
__device__ float g_k[SEQ * KVDIM];
__device__ float g_v[SEQ * KVDIM];
__device__ float g_y[SEQ * DIM];

// ---------------------------------------------------------------------------
// GEMM (NT): C[M,N] = A[M,K] * B[N,K]^T, all row-major fp32.
// 128x128 block tile, BK=8, 256 threads, 8x8 register tile per thread.
// ---------------------------------------------------------------------------
__global__ __launch_bounds__(256, 2)
void gemm_nt_kernel(const float* __restrict__ A, const float* __restrict__ B,
                    float* __restrict__ C, int M, int N, int K) {
    __shared__ float As[8][128];
    __shared__ float Bs[8][128];

    const int tid = threadIdx.x;
    const int bm  = blockIdx.y * 128;
    const int bn  = blockIdx.x * 128;

    // global->smem load mapping: each thread loads one float4 from A and one from B
    const int lr = tid >> 1;          // 0..127 : row within tile
    const int lc = (tid & 1) << 2;    // 0 or 4 : k-offset within BK

    // compute mapping: 16x16 thread grid, each does 8x8
    const int tx = (tid & 15) << 3;   // col offset 0..120
    const int ty = (tid >> 4) << 3;   // row offset 0..120

    const float* Ap = A + (size_t)(bm + lr) * K + lc;
    const float* Bp = B + (size_t)(bn + lr) * K + lc;

    float acc[8][8];
#pragma unroll
    for (int i = 0; i < 8; i++)
#pragma unroll
        for (int j = 0; j < 8; j++) acc[i][j] = 0.0f;

    for (int k0 = 0; k0 < K; k0 += 8) {
        float4 a4 = *(const float4*)(Ap + k0);
        float4 b4 = *(const float4*)(Bp + k0);
        As[lc + 0][lr] = a4.x; As[lc + 1][lr] = a4.y;
        As[lc + 2][lr] = a4.z; As[lc + 3][lr] = a4.w;
        Bs[lc + 0][lr] = b4.x; Bs[lc + 1][lr] = b4.y;
        Bs[lc + 2][lr] = b4.z; Bs[lc + 3][lr] = b4.w;
        __syncthreads();

#pragma unroll
        for (int kk = 0; kk < 8; kk++) {
            float a[8], b[8];
            *(float4*)&a[0] = *(const float4*)&As[kk][ty];
            *(float4*)&a[4] = *(const float4*)&As[kk][ty + 4];
            *(float4*)&b[0] = *(const float4*)&Bs[kk][tx];
            *(float4*)&b[4] = *(const float4*)&Bs[kk][tx + 4];
#pragma unroll
            for (int i = 0; i < 8; i++)
#pragma unroll
                for (int j = 0; j < 8; j++)
                    acc[i][j] = fmaf(a[i], b[j], acc[i][j]);
        }
        __syncthreads();
    }

#pragma unroll
    for (int i = 0; i < 8; i++) {
        float* Cp = C + (size_t)(bm + ty + i) * N + bn + tx;
        *(float4*)(Cp + 0) = make_float4(acc[i][0], acc[i][1], acc[i][2], acc[i][3]);
        *(float4*)(Cp + 4) = make_float4(acc[i][4], acc[i][5], acc[i][6], acc[i][7]);
    }
}

// ---------------------------------------------------------------------------
// RoPE over Q (32 heads) and K (8 heads), interleaved pairs (re, im).
// ---------------------------------------------------------------------------
__global__ void rope_kernel(float* __restrict__ q, float* __restrict__ k,
                            const float* __restrict__ fc, const float* __restrict__ fs) {
    const int PAIRS = HD / 2;   // 64
    int idx = blockIdx.x * blockDim.x + threadIdx.x;
    const int TOT = SEQ * (NH + NKV) * PAIRS;
    if (idx >= TOT) return;
    int p = idx % PAIRS;
    int h = (idx / PAIRS) % (NH + NKV);
    int s = idx / (PAIRS * (NH + NKV));
    float c  = fc[s * PAIRS + p];
    float sn = fs[s * PAIRS + p];
    float* base;
    if (h < NH) base = q + (size_t)s * DIM + h * HD + 2 * p;
    else        base = k + (size_t)s * KVDIM + (h - NH) * HD + 2 * p;
    float2 ri = *(float2*)base;
    float2 outv;
    outv.x = ri.x * c - ri.y * sn;
    outv.y = ri.x * sn + ri.y * c;
    *(float2*)base = outv;
}

// ---------------------------------------------------------------------------
// Flash attention (causal, GQA). One block = 128 query rows x 1 head.
// 512 threads = 16 warps; warp w owns query rows [w*8, w*8+8).
// Per lane: score cols {lane, lane+32}, output cols [lane*4, lane*4+4).
// ---------------------------------------------------------------------------
#define BQ   128
#define BK   64
#define PSTR 132                    // padded fp32 row stride (16B-aligned, conflict-free)
#define PPAD 65                     // Ps row stride
#define FLASH_SMEM ((BQ * PSTR + 2 * BK * PSTR + BQ * PPAD) * 4)

__global__ __launch_bounds__(512, 1)
void flash_kernel(const float* __restrict__ Q, const float* __restrict__ K,
                  const float* __restrict__ V, float* __restrict__ Y) {
    extern __shared__ float sm[];
    float* Qs = sm;                       // BQ x PSTR
    float* Ks = Qs + BQ * PSTR;           // BK x PSTR
    float* Vs = Ks + BK * PSTR;           // BK x PSTR
    float* Ps = Vs + BK * PSTR;           // BQ x PPAD

    const int tid   = threadIdx.x;
    const int lane  = tid & 31;
    const int w     = tid >> 5;
    const int h     = blockIdx.y;
    const int kh    = h >> 2;             // GQA: 4 query heads per kv head
    const int qbase = blockIdx.x * BQ;
    const float scale = 0.08838834764831845f;  // 1/sqrt(128)

    // Load + pre-scale Q tile (128x128 floats, 8 float4 per thread)
#pragma unroll
    for (int i = 0; i < 8; i++) {
        int lin = tid + i * 512;          // 0..4095
        int row = lin >> 5;
        int c4  = (lin & 31) << 2;
        float4 v = *(const float4*)(Q + (size_t)(qbase + row) * DIM + h * HD + c4);
        float* dst = Qs + row * PSTR + c4;
        dst[0] = v.x * scale; dst[1] = v.y * scale;
        dst[2] = v.z * scale; dst[3] = v.w * scale;
    }

    float  m[8], lsum[8];
    float4 o[8];
#pragma unroll
    for (int r = 0; r < 8; r++) {
        m[r] = -1e30f; lsum[r] = 0.0f;
        o[r] = make_float4(0.f, 0.f, 0.f, 0.f);
    }

    const int r0 = w * 8;
    const int ntiles = (qbase + BQ) / BK;

    for (int kt = 0; kt < ntiles; kt++) {
        const int kbase = kt * BK;
        __syncthreads();   // Qs visible (iter 0) / Ks,Vs reuse safe (iter>0)

        // Load K,V tiles (64x128 each, 4 float4 per thread per tensor)
#pragma unroll
        for (int i = 0; i < 4; i++) {
            int lin = tid + i * 512;      // 0..2047
            int row = lin >> 5;
            int c4  = (lin & 31) << 2;
            *(float4*)(Ks + row * PSTR + c4) =
                *(const float4*)(K + (size_t)(kbase + row) * KVDIM + kh * HD + c4);
            *(float4*)(Vs + row * PSTR + c4) =
                *(const float4*)(V + (size_t)(kbase + row) * KVDIM + kh * HD + c4);
        }
        __syncthreads();

        // Scores: 8 rows x 2 cols per lane, dot over 128
        float acc0[8], acc1[8];
#pragma unroll
        for (int r = 0; r < 8; r++) { acc0[r] = 0.f; acc1[r] = 0.f; }
#pragma unroll 4
        for (int d4 = 0; d4 < 32; d4++) {
            float4 kA = *(const float4*)(Ks + lane * PSTR + d4 * 4);
            float4 kB = *(const float4*)(Ks + (lane + 32) * PSTR + d4 * 4);
#pragma unroll
            for (int r = 0; r < 8; r++) {
                float4 q4 = *(const float4*)(Qs + (r0 + r) * PSTR + d4 * 4);
                acc0[r] = fmaf(q4.x, kA.x, acc0[r]);
                acc0[r] = fmaf(q4.y, kA.y, acc0[r]);
                acc0[r] = fmaf(q4.z, kA.z, acc0[r]);
                acc0[r] = fmaf(q4.w, kA.w, acc0[r]);
                acc1[r] = fmaf(q4.x, kB.x, acc1[r]);
                acc1[r] = fmaf(q4.y, kB.y, acc1[r]);
                acc1[r] = fmaf(q4.z, kB.z, acc1[r]);
                acc1[r] = fmaf(q4.w, kB.w, acc1[r]);
            }
        }

        // Causal mask + online softmax (per warp row state, replicated per lane)
#pragma unroll
        for (int r = 0; r < 8; r++) {
            int rg = qbase + r0 + r;
            if (kbase + lane > rg)      acc0[r] = -1e30f;
            if (kbase + lane + 32 > rg) acc1[r] = -1e30f;
            float rm = fmaxf(acc0[r], acc1[r]);
#pragma unroll
            for (int off = 16; off > 0; off >>= 1)
                rm = fmaxf(rm, __shfl_xor_sync(0xFFFFFFFFu, rm, off));
            float mn = fmaxf(m[r], rm);
            float alpha = __expf(m[r] - mn);
            float p0 = __expf(acc0[r] - mn);
            float p1 = __expf(acc1[r] - mn);
            float ps = p0 + p1;
#pragma unroll
            for (int off = 16; off > 0; off >>= 1)
                ps += __shfl_xor_sync(0xFFFFFFFFu, ps, off);
            lsum[r] = lsum[r] * alpha + ps;
            m[r] = mn;
            o[r].x *= alpha; o[r].y *= alpha; o[r].z *= alpha; o[r].w *= alpha;
            Ps[(r0 + r) * PPAD + lane]      = p0;
            Ps[(r0 + r) * PPAD + lane + 32] = p1;
        }
        __syncwarp();

        // O += P @ V : each lane owns cols [lane*4, lane*4+4) of all 8 rows
#pragma unroll 4
        for (int kk = 0; kk < BK; kk++) {
            float4 v4 = *(const float4*)(Vs + kk * PSTR + lane * 4);
#pragma unroll
            for (int r = 0; r < 8; r++) {
                float p = Ps[(r0 + r) * PPAD + kk];
                o[r].x = fmaf(p, v4.x, o[r].x);
                o[r].y = fmaf(p, v4.y, o[r].y);
                o[r].z = fmaf(p, v4.z, o[r].z);
                o[r].w = fmaf(p, v4.w, o[r].w);
            }
        }
    }

    // Epilogue: normalize and store
#pragma unroll
    for (int r = 0; r < 8; r++) {
        float inv = 1.0f / lsum[r];
        float4 ov = make_float4(o[r].x * inv, o[r].y * inv, o[r].z * inv, o[r].w * inv);
        *(float4*)(Y + (size_t)(qbase + r0 + r) * DIM + h * HD + lane * 4) = ov;
    }
}

// ---------------------------------------------------------------------------
// Launch
// ---------------------------------------------------------------------------
extern "C" void kernel_launch(void* const* d_in, const int* in_sizes, int n_in,
                              void* d_out, int out_size) {
    const float* x  = (const float*)d_in[0];
    const float* wq = (const float*)d_in[1];
    const float* wk = (const float*)d_in[2];
    const float* wv = (const float*)d_in[3];
    const float* wo = (const float*)d_in[4];
    const float* fc = (const float*)d_in[5];
    const float* fs = (const float*)d_in[6];
    float* out = (float*)d_out;

    float *q, *k, *v, *y;
    cudaGetSymbolAddress((void**)&q, g_q);
    cudaGetSymbolAddress((void**)&k, g_k);
    cudaGetSymbolAddress((void**)&v, g_v);
    cudaGetSymbolAddress((void**)&y, g_y);

    // Projections: Q, K, V
    gemm_nt_kernel<<<dim3(DIM / 128, SEQ / 128), 256>>>(x, wq, q, SEQ, DIM, DIM);
    gemm_nt_kernel<<<dim3(KVDIM / 128, SEQ / 128), 256>>>(x, wk, k, SEQ, KVDIM, DIM);
    gemm_nt_kernel<<<dim3(KVDIM / 128, SEQ / 128), 256>>>(x, wv, v, SEQ, KVDIM, DIM);

    // RoPE on Q and K
    int tot = SEQ * (NH + NKV) * (HD / 2);
    rope_kernel<<<(tot + 255) / 256, 256>>>(q, k, fc, fs);

    // Causal GQA flash attention
    cudaFuncSetAttribute(flash_kernel, cudaFuncAttributeMaxDynamicSharedMemorySize,
                         FLASH_SMEM);
    flash_kernel<<<dim3(SEQ / BQ, NH), 512, FLASH_SMEM>>>(q, k, v, y);

    // Output projection
    gemm_nt_kernel<<<dim3(DIM / 128, SEQ / 128), 256>>>(y, wo, out, SEQ, DIM, DIM);
}

// round 3
// speedup vs baseline: 2.1321x; 2.1321x over previous
#include <cuda_runtime.h>
#include <math.h>

#define SEQ   2048
#define DIM   4096
#define NH    32
#define NKV   8
#define HD    128
#define KVDIM (NKV * HD)   // 1024
#define NREP  (NH / NKV)   // 4

// Scratch (device globals: allocation-free rule)
__device__ float g_q[SEQ * DIM];
__device__ float g_k[SEQ * KVDIM];
__device__ float g_v[SEQ * KVDIM];
__device__ float g_y[SEQ * DIM];

// ---------------------------------------------------------------------------
// TF32 tensor-core GEMM (NT): C[M,N] = A[M,K] * B[N,K]^T, row-major fp32 I/O.
// 128x128 block tile, BK=32, 256 threads = 8 warps, warp tile 64x32
// (4x4 grid of m16n8k8 mma). Smem row stride 36 -> conflict-free frag loads.
// ---------------------------------------------------------------------------
#define GSTR 36   // smem row stride in floats: bank=(4*grp+tig)%32, conflict-free

__device__ __forceinline__ unsigned f2tf32(float x) {
    unsigned r;
    asm("cvt.rna.tf32.f32 %0, %1;" : "=r"(r) : "f"(x));
    return r;
}

__global__ __launch_bounds__(256, 2)
void gemm_tf32_kernel(const float* __restrict__ A, const float* __restrict__ B,
                      float* __restrict__ C, int M, int N, int K) {
    __shared__ float As[128 * GSTR];
    __shared__ float Bs[128 * GSTR];

    const int tid  = threadIdx.x;
    const int lane = tid & 31;
    const int wid  = tid >> 5;
    const int grp  = lane >> 2;     // 0..7
    const int tig  = lane & 3;      // 0..3

    const int bm = blockIdx.y * 128;
    const int bn = blockIdx.x * 128;
    const int wm = (wid & 1) * 64;  // warp m-offset
    const int wn = (wid >> 1) * 32; // warp n-offset

    // loader mapping: 256 threads, each covers 16 consecutive floats of one row
    const int lrow = tid >> 1;            // 0..127
    const int lcb  = (tid & 1) * 16;      // 0 or 16

    const float* Ap = A + (size_t)(bm + lrow) * K + lcb;
    const float* Bp = B + (size_t)(bn + lrow) * K + lcb;

    float acc[4][4][4];
#pragma unroll
    for (int i = 0; i < 4; i++)
#pragma unroll
        for (int j = 0; j < 4; j++)
#pragma unroll
            for (int t = 0; t < 4; t++) acc[i][j][t] = 0.0f;

    for (int k0 = 0; k0 < K; k0 += 32) {
        // global -> smem (convert to tf32 bits on the way in)
#pragma unroll
        for (int q4 = 0; q4 < 4; q4++) {
            float4 av = *(const float4*)(Ap + k0 + q4 * 4);
            float4 bv = *(const float4*)(Bp + k0 + q4 * 4);
            float* ad = As + lrow * GSTR + lcb + q4 * 4;
            float* bd = Bs + lrow * GSTR + lcb + q4 * 4;
            // 8-byte aligned (GSTR even, offsets multiple of 4): use float2
            ((float2*)ad)[0] = make_float2(__uint_as_float(f2tf32(av.x)),
                                           __uint_as_float(f2tf32(av.y)));
            ((float2*)ad)[1] = make_float2(__uint_as_float(f2tf32(av.z)),
                                           __uint_as_float(f2tf32(av.w)));
            ((float2*)bd)[0] = make_float2(__uint_as_float(f2tf32(bv.x)),
                                           __uint_as_float(f2tf32(bv.y)));
            ((float2*)bd)[1] = make_float2(__uint_as_float(f2tf32(bv.z)),
                                           __uint_as_float(f2tf32(bv.w)));
        }
        __syncthreads();

#pragma unroll
        for (int kk = 0; kk < 4; kk++) {      // 4 k8-steps per BK=32
            const int ko = kk * 8;
            unsigned af[4][4], bf[4][2];
#pragma unroll
            for (int i = 0; i < 4; i++) {
                const float* base = As + (wm + i * 16 + grp) * GSTR + ko + tig;
                af[i][0] = __float_as_uint(base[0]);
                af[i][1] = __float_as_uint(base[8 * GSTR]);
                af[i][2] = __float_as_uint(base[4]);
                af[i][3] = __float_as_uint(base[8 * GSTR + 4]);
            }
#pragma unroll
            for (int j = 0; j < 4; j++) {
                const float* base = Bs + (wn + j * 8 + grp) * GSTR + ko + tig;
                bf[j][0] = __float_as_uint(base[0]);
                bf[j][1] = __float_as_uint(base[4]);
            }
#pragma unroll
            for (int i = 0; i < 4; i++)
#pragma unroll
                for (int j = 0; j < 4; j++) {
                    asm volatile(
                        "mma.sync.aligned.m16n8k8.row.col.f32.tf32.tf32.f32 "
                        "{%0,%1,%2,%3}, {%4,%5,%6,%7}, {%8,%9}, {%0,%1,%2,%3};"
                        : "+f"(acc[i][j][0]), "+f"(acc[i][j][1]),
                          "+f"(acc[i][j][2]), "+f"(acc[i][j][3])
                        : "r"(af[i][0]), "r"(af[i][1]), "r"(af[i][2]), "r"(af[i][3]),
                          "r"(bf[j][0]), "r"(bf[j][1]));
                }
        }
        __syncthreads();
    }

    // epilogue
#pragma unroll
    for (int i = 0; i < 4; i++) {
#pragma unroll
        for (int j = 0; j < 4; j++) {
            int r   = bm + wm + i * 16 + grp;
            int col = bn + wn + j * 8 + tig * 2;
            *(float2*)(C + (size_t)r * N + col) =
                make_float2(acc[i][j][0], acc[i][j][1]);
            *(float2*)(C + (size_t)(r + 8) * N + col) =
                make_float2(acc[i][j][2], acc[i][j][3]);
        }
    }
}

// ---------------------------------------------------------------------------
// RoPE over Q (32 heads) and K (8 heads), interleaved pairs (re, im).
// ---------------------------------------------------------------------------
__global__ void rope_kernel(float* __restrict__ q, float* __restrict__ k,
                            const float* __restrict__ fc, const float* __restrict__ fs) {
    const int PAIRS = HD / 2;   // 64
    int idx = blockIdx.x * blockDim.x + threadIdx.x;
    const int TOT = SEQ * (NH + NKV) * PAIRS;
    if (idx >= TOT) return;
    int p = idx % PAIRS;
    int h = (idx / PAIRS) % (NH + NKV);
    int s = idx / (PAIRS * (NH + NKV));
    float c  = fc[s * PAIRS + p];
    float sn = fs[s * PAIRS + p];
    float* base;
    if (h < NH) base = q + (size_t)s * DIM + h * HD + 2 * p;
    else        base = k + (size_t)s * KVDIM + (h - NH) * HD + 2 * p;
    float2 ri = *(float2*)base;
    float2 outv;
    outv.x = ri.x * c - ri.y * sn;
    outv.y = ri.x * sn + ri.y * c;
    *(float2*)base = outv;
}

// ---------------------------------------------------------------------------
// Flash attention (causal, GQA). One block = 128 query rows x 1 head.
// 512 threads = 16 warps; warp w owns query rows [w*8, w*8+8).
// ---------------------------------------------------------------------------
#define BQ   128
#define BK   64
#define PSTR 132
#define PPAD 65
#define FLASH_SMEM ((BQ * PSTR + 2 * BK * PSTR + BQ * PPAD) * 4)

__global__ __launch_bounds__(512, 1)
void flash_kernel(const float* __restrict__ Q, const float* __restrict__ K,
                  const float* __restrict__ V, float* __restrict__ Y) {
    extern __shared__ float sm[];
    float* Qs = sm;
    float* Ks = Qs + BQ * PSTR;
    float* Vs = Ks + BK * PSTR;
    float* Ps = Vs + BK * PSTR;

    const int tid   = threadIdx.x;
    const int lane  = tid & 31;
    const int w     = tid >> 5;
    const int h     = blockIdx.y;
    const int kh    = h >> 2;
    const int qbase = blockIdx.x * BQ;
    const float scale = 0.08838834764831845f;

#pragma unroll
    for (int i = 0; i < 8; i++) {
        int lin = tid + i * 512;
        int row = lin >> 5;
        int c4  = (lin & 31) << 2;
        float4 v = *(const float4*)(Q + (size_t)(qbase + row) * DIM + h * HD + c4);
        float* dst = Qs + row * PSTR + c4;
        dst[0] = v.x * scale; dst[1] = v.y * scale;
        dst[2] = v.z * scale; dst[3] = v.w * scale;
    }

    float  m[8], lsum[8];
    float4 o[8];
#pragma unroll
    for (int r = 0; r < 8; r++) {
        m[r] = -1e30f; lsum[r] = 0.0f;
        o[r] = make_float4(0.f, 0.f, 0.f, 0.f);
    }

    const int r0 = w * 8;
    const int ntiles = (qbase + BQ) / BK;

    for (int kt = 0; kt < ntiles; kt++) {
        const int kbase = kt * BK;
        __syncthreads();

#pragma unroll
        for (int i = 0; i < 4; i++) {
            int lin = tid + i * 512;
            int row = lin >> 5;
            int c4  = (lin & 31) << 2;
            *(float4*)(Ks + row * PSTR + c4) =
                *(const float4*)(K + (size_t)(kbase + row) * KVDIM + kh * HD + c4);
            *(float4*)(Vs + row * PSTR + c4) =
                *(const float4*)(V + (size_t)(kbase + row) * KVDIM + kh * HD + c4);
        }
        __syncthreads();

        float acc0[8], acc1[8];
#pragma unroll
        for (int r = 0; r < 8; r++) { acc0[r] = 0.f; acc1[r] = 0.f; }
#pragma unroll 4
        for (int d4 = 0; d4 < 32; d4++) {
            float4 kA = *(const float4*)(Ks + lane * PSTR + d4 * 4);
            float4 kB = *(const float4*)(Ks + (lane + 32) * PSTR + d4 * 4);
#pragma unroll
            for (int r = 0; r < 8; r++) {
                float4 q4 = *(const float4*)(Qs + (r0 + r) * PSTR + d4 * 4);
                acc0[r] = fmaf(q4.x, kA.x, acc0[r]);
                acc0[r] = fmaf(q4.y, kA.y, acc0[r]);
                acc0[r] = fmaf(q4.z, kA.z, acc0[r]);
                acc0[r] = fmaf(q4.w, kA.w, acc0[r]);
                acc1[r] = fmaf(q4.x, kB.x, acc1[r]);
                acc1[r] = fmaf(q4.y, kB.y, acc1[r]);
                acc1[r] = fmaf(q4.z, kB.z, acc1[r]);
                acc1[r] = fmaf(q4.w, kB.w, acc1[r]);
            }
        }

#pragma unroll
        for (int r = 0; r < 8; r++) {
            int rg = qbase + r0 + r;
            if (kbase + lane > rg)      acc0[r] = -1e30f;
            if (kbase + lane + 32 > rg) acc1[r] = -1e30f;
            float rm = fmaxf(acc0[r], acc1[r]);
#pragma unroll
            for (int off = 16; off > 0; off >>= 1)
                rm = fmaxf(rm, __shfl_xor_sync(0xFFFFFFFFu, rm, off));
            float mn = fmaxf(m[r], rm);
            float alpha = __expf(m[r] - mn);
            float p0 = __expf(acc0[r] - mn);
            float p1 = __expf(acc1[r] - mn);
            float ps = p0 + p1;
#pragma unroll
            for (int off = 16; off > 0; off >>= 1)
                ps += __shfl_xor_sync(0xFFFFFFFFu, ps, off);
            lsum[r] = lsum[r] * alpha + ps;
            m[r] = mn;
            o[r].x *= alpha; o[r].y *= alpha; o[r].z *= alpha; o[r].w *= alpha;
            Ps[(r0 + r) * PPAD + lane]      = p0;
            Ps[(r0 + r) * PPAD + lane + 32] = p1;
        }
        __syncwarp();

#pragma unroll 4
        for (int kk = 0; kk < BK; kk++) {
            float4 v4 = *(const float4*)(Vs + kk * PSTR + lane * 4);
#pragma unroll
            for (int r = 0; r < 8; r++) {
                float p = Ps[(r0 + r) * PPAD + kk];
                o[r].x = fmaf(p, v4.x, o[r].x);
                o[r].y = fmaf(p, v4.y, o[r].y);
                o[r].z = fmaf(p, v4.z, o[r].z);
                o[r].w = fmaf(p, v4.w, o[r].w);
            }
        }
    }

#pragma unroll
    for (int r = 0; r < 8; r++) {
        float inv = 1.0f / lsum[r];
        float4 ov = make_float4(o[r].x * inv, o[r].y * inv, o[r].z * inv, o[r].w * inv);
        *(float4*)(Y + (size_t)(qbase + r0 + r) * DIM + h * HD + lane * 4) = ov;
    }
}

// ---------------------------------------------------------------------------
// Launch
// ---------------------------------------------------------------------------
extern "C" void kernel_launch(void* const* d_in, const int* in_sizes, int n_in,
                              void* d_out, int out_size) {
    const float* x  = (const float*)d_in[0];
    const float* wq = (const float*)d_in[1];
    const float* wk = (const float*)d_in[2];
    const float* wv = (const float*)d_in[3];
    const float* wo = (const float*)d_in[4];
    const float* fc = (const float*)d_in[5];
    const float* fs = (const float*)d_in[6];
    float* out = (float*)d_out;

    float *q, *k, *v, *y;
    cudaGetSymbolAddress((void**)&q, g_q);
    cudaGetSymbolAddress((void**)&k, g_k);
    cudaGetSymbolAddress((void**)&v, g_v);
    cudaGetSymbolAddress((void**)&y, g_y);

    // Projections on tensor cores (tf32)
    gemm_tf32_kernel<<<dim3(DIM / 128, SEQ / 128), 256>>>(x, wq, q, SEQ, DIM, DIM);
    gemm_tf32_kernel<<<dim3(KVDIM / 128, SEQ / 128), 256>>>(x, wk, k, SEQ, KVDIM, DIM);
    gemm_tf32_kernel<<<dim3(KVDIM / 128, SEQ / 128), 256>>>(x, wv, v, SEQ, KVDIM, DIM);

    // RoPE on Q and K
    int tot = SEQ * (NH + NKV) * (HD / 2);
    rope_kernel<<<(tot + 255) / 256, 256>>>(q, k, fc, fs);

    // Causal GQA flash attention
    cudaFuncSetAttribute(flash_kernel, cudaFuncAttributeMaxDynamicSharedMemorySize,
                         FLASH_SMEM);
    flash_kernel<<<dim3(SEQ / BQ, NH), 512, FLASH_SMEM>>>(q, k, v, y);

    // Output projection (tf32)
    gemm_tf32_kernel<<<dim3(DIM / 128, SEQ / 128), 256>>>(y, wo, out, SEQ, DIM, DIM);
}

// round 5
// speedup vs baseline: 2.8879x; 1.3545x over previous
#include <cuda_runtime.h>
#include <math.h>

#define SEQ   2048
#define DIM   4096
#define NH    32
#define NKV   8
#define HD    128
#define KVDIM (NKV * HD)   // 1024

// Scratch (device globals: allocation-free rule)
__device__ float g_q[SEQ * DIM];
__device__ float g_k[SEQ * KVDIM];
__device__ float g_v[SEQ * KVDIM];
__device__ float g_y[SEQ * DIM];

__device__ __forceinline__ unsigned f2tf32(float x) {
    unsigned r;
    asm("cvt.rna.tf32.f32 %0, %1;" : "=r"(r) : "f"(x));
    return r;
}
__device__ __forceinline__ float tf32f(float x) {
    return __uint_as_float(f2tf32(x));
}
__device__ __forceinline__ void cp16(void* smem_dst, const void* gsrc) {
    unsigned d = (unsigned)__cvta_generic_to_shared(smem_dst);
    asm volatile("cp.async.cg.shared.global [%0], [%1], 16;" :: "r"(d), "l"(gsrc));
}
__device__ __forceinline__ void mma_tf32(float c[4], const unsigned a[4], const unsigned b[2]) {
    asm volatile(
        "mma.sync.aligned.m16n8k8.row.col.f32.tf32.tf32.f32 "
        "{%0,%1,%2,%3}, {%4,%5,%6,%7}, {%8,%9}, {%0,%1,%2,%3};"
        : "+f"(c[0]), "+f"(c[1]), "+f"(c[2]), "+f"(c[3])
        : "r"(a[0]), "r"(a[1]), "r"(a[2]), "r"(a[3]), "r"(b[0]), "r"(b[1]));
}

// ---------------------------------------------------------------------------
// TF32 GEMM (NT): C[M,N] = A[M,K] * B[N,K]^T.  128x128 tile, BK=32, 256 thr,
// 8 warps x (64x32 warp tile), cp.async 2-stage double buffer.
// ---------------------------------------------------------------------------
#define GSTR 36
#define GEMM_SMEM (2 * 2 * 128 * GSTR * 4)   // 73728 B

__global__ __launch_bounds__(256, 2)
void gemm_tf32_kernel(const float* __restrict__ A, const float* __restrict__ B,
                      float* __restrict__ C, int M, int N, int K) {
    extern __shared__ float gsm[];
    float* As = gsm;                    // [2][128*GSTR]
    float* Bs = gsm + 2 * 128 * GSTR;   // [2][128*GSTR]

    const int tid  = threadIdx.x;
    const int lane = tid & 31;
    const int wid  = tid >> 5;
    const int grp  = lane >> 2;
    const int tig  = lane & 3;

    const int bm = blockIdx.y * 128;
    const int bn = blockIdx.x * 128;
    const int wm = (wid & 1) * 64;
    const int wn = (wid >> 1) * 32;

    const int lrow = tid >> 1;
    const int lcb  = (tid & 1) * 16;

    const float* Ap = A + (size_t)(bm + lrow) * K + lcb;
    const float* Bp = B + (size_t)(bn + lrow) * K + lcb;

    float acc[4][4][4];
#pragma unroll
    for (int i = 0; i < 4; i++)
#pragma unroll
        for (int j = 0; j < 4; j++)
#pragma unroll
            for (int t = 0; t < 4; t++) acc[i][j][t] = 0.0f;

    const int nk = K / 32;

    // prologue: stage 0
#pragma unroll
    for (int q4 = 0; q4 < 4; q4++) {
        cp16(As + lrow * GSTR + lcb + q4 * 4, Ap + q4 * 4);
        cp16(Bs + lrow * GSTR + lcb + q4 * 4, Bp + q4 * 4);
    }
    asm volatile("cp.async.commit_group;");

    for (int t = 0; t < nk; t++) {
        if (t + 1 < nk) {
            int buf = (t + 1) & 1;
            const float* Apn = Ap + (t + 1) * 32;
            const float* Bpn = Bp + (t + 1) * 32;
#pragma unroll
            for (int q4 = 0; q4 < 4; q4++) {
                cp16(As + buf * 128 * GSTR + lrow * GSTR + lcb + q4 * 4, Apn + q4 * 4);
                cp16(Bs + buf * 128 * GSTR + lrow * GSTR + lcb + q4 * 4, Bpn + q4 * 4);
            }
            asm volatile("cp.async.commit_group;");
            asm volatile("cp.async.wait_group 1;");
        } else {
            asm volatile("cp.async.wait_group 0;");
        }
        __syncthreads();

        const float* Ab = As + (t & 1) * 128 * GSTR;
        const float* Bb = Bs + (t & 1) * 128 * GSTR;
#pragma unroll
        for (int kk = 0; kk < 4; kk++) {
            const int ko = kk * 8;
            unsigned af[4][4], bf[4][2];
#pragma unroll
            for (int i = 0; i < 4; i++) {
                const float* base = Ab + (wm + i * 16 + grp) * GSTR + ko + tig;
                af[i][0] = f2tf32(base[0]);
                af[i][1] = f2tf32(base[8 * GSTR]);
                af[i][2] = f2tf32(base[4]);
                af[i][3] = f2tf32(base[8 * GSTR + 4]);
            }
#pragma unroll
            for (int j = 0; j < 4; j++) {
                const float* base = Bb + (wn + j * 8 + grp) * GSTR + ko + tig;
                bf[j][0] = f2tf32(base[0]);
                bf[j][1] = f2tf32(base[4]);
            }
#pragma unroll
            for (int i = 0; i < 4; i++)
#pragma unroll
                for (int j = 0; j < 4; j++)
                    mma_tf32(acc[i][j], af[i], bf[j]);
        }
        __syncthreads();
    }

#pragma unroll
    for (int i = 0; i < 4; i++)
#pragma unroll
        for (int j = 0; j < 4; j++) {
            int r   = bm + wm + i * 16 + grp;
            int col = bn + wn + j * 8 + tig * 2;
            *(float2*)(C + (size_t)r * N + col) =
                make_float2(acc[i][j][0], acc[i][j][1]);
            *(float2*)(C + (size_t)(r + 8) * N + col) =
                make_float2(acc[i][j][2], acc[i][j][3]);
        }
}

// ---------------------------------------------------------------------------
// RoPE over Q (32 heads) and K (8 heads).
// ---------------------------------------------------------------------------
__global__ void rope_kernel(float* __restrict__ q, float* __restrict__ k,
                            const float* __restrict__ fc, const float* __restrict__ fs) {
    const int PAIRS = HD / 2;
    int idx = blockIdx.x * blockDim.x + threadIdx.x;
    const int TOT = SEQ * (NH + NKV) * PAIRS;
    if (idx >= TOT) return;
    int p = idx % PAIRS;
    int h = (idx / PAIRS) % (NH + NKV);
    int s = idx / (PAIRS * (NH + NKV));
    float c  = fc[s * PAIRS + p];
    float sn = fs[s * PAIRS + p];
    float* base;
    if (h < NH) base = q + (size_t)s * DIM + h * HD + 2 * p;
    else        base = k + (size_t)s * KVDIM + (h - NH) * HD + 2 * p;
    float2 ri = *(float2*)base;
    float2 outv;
    outv.x = ri.x * c - ri.y * sn;
    outv.y = ri.x * sn + ri.y * c;
    *(float2*)base = outv;
}

// ---------------------------------------------------------------------------
// Tensor-core flash attention (causal, GQA).
// Block = 128 q-rows x 1 head. 256 threads = 8 warps, warp owns 16 q-rows.
// S = Q K^T via mma.tf32 (C-frag), online softmax in registers,
// P -> smem (tf32) -> A-frags, O += P V via mma.tf32.
// ---------------------------------------------------------------------------
#define BQ    128
#define BK    64
#define FSTR  136   // stride % 32 == 8 -> conflict-free fragment LDS
#define PSTR2 72
#define FLASH_SMEM ((BQ * FSTR + 2 * BK * FSTR + BQ * PSTR2) * 4)

__global__ __launch_bounds__(256, 1)
void flash_tc_kernel(const float* __restrict__ Q, const float* __restrict__ K,
                     const float* __restrict__ V, float* __restrict__ Y) {
    extern __shared__ float sm[];
    float* Qs = sm;                  // 128 x FSTR
    float* Ks = Qs + BQ * FSTR;      // 64 x FSTR
    float* Vs = Ks + BK * FSTR;      // 64 x FSTR
    float* Ps = Vs + BK * FSTR;      // 128 x PSTR2

    const int tid  = threadIdx.x;
    const int lane = tid & 31;
    const int w    = tid >> 5;
    const int grp  = lane >> 2;
    const int tig  = lane & 3;
    const int h    = blockIdx.y;
    const int kh   = h >> 2;
    const int qbase = blockIdx.x * BQ;
    const int m0   = w * 16;                 // warp row base
    const float scale = 0.08838834764831845f;

    // Load Q tile (pre-scaled, tf32-rounded): 4096 float4, 16 per thread
#pragma unroll
    for (int i = 0; i < 16; i++) {
        int lin = tid + i * 256;
        int row = lin >> 5;
        int c4  = (lin & 31) << 2;
        float4 v = *(const float4*)(Q + (size_t)(qbase + row) * DIM + h * HD + c4);
        float* dst = Qs + row * FSTR + c4;
        dst[0] = tf32f(v.x * scale); dst[1] = tf32f(v.y * scale);
        dst[2] = tf32f(v.z * scale); dst[3] = tf32f(v.w * scale);
    }

    float m0s = -1e30f, m1s = -1e30f, l0 = 0.0f, l1 = 0.0f;
    float o[16][4];
#pragma unroll
    for (int nt = 0; nt < 16; nt++)
#pragma unroll
        for (int t = 0; t < 4; t++) o[nt][t] = 0.0f;

    const int rowg0 = qbase + m0 + grp;
    const int rowg1 = rowg0 + 8;
    const int ntiles = (qbase + BQ) / BK;

    for (int kt = 0; kt < ntiles; kt++) {
        const int kbase = kt * BK;
        __syncthreads();

        // Load K,V tiles (tf32-rounded): 2048 float4 each, 8 per thread
#pragma unroll
        for (int i = 0; i < 8; i++) {
            int lin = tid + i * 256;
            int row = lin >> 5;
            int c4  = (lin & 31) << 2;
            float4 kv = *(const float4*)(K + (size_t)(kbase + row) * KVDIM + kh * HD + c4);
            float4 vv = *(const float4*)(V + (size_t)(kbase + row) * KVDIM + kh * HD + c4);
            float* kd = Ks + row * FSTR + c4;
            float* vd = Vs + row * FSTR + c4;
            kd[0] = tf32f(kv.x); kd[1] = tf32f(kv.y);
            kd[2] = tf32f(kv.z); kd[3] = tf32f(kv.w);
            vd[0] = tf32f(vv.x); vd[1] = tf32f(vv.y);
            vd[2] = tf32f(vv.z); vd[3] = tf32f(vv.w);
        }
        __syncthreads();

        // S = Q K^T : warp computes 16 x 64 (8 n-tiles)
        float sacc[8][4];
#pragma unroll
        for (int nt = 0; nt < 8; nt++)
#pragma unroll
            for (int t = 0; t < 4; t++) sacc[nt][t] = 0.0f;

#pragma unroll
        for (int k8 = 0; k8 < 16; k8++) {
            const int ko = k8 * 8;
            unsigned a[4];
            const float* ab = Qs + (m0 + grp) * FSTR + ko + tig;
            a[0] = __float_as_uint(ab[0]);
            a[1] = __float_as_uint(ab[8 * FSTR]);
            a[2] = __float_as_uint(ab[4]);
            a[3] = __float_as_uint(ab[8 * FSTR + 4]);
#pragma unroll
            for (int nt = 0; nt < 8; nt++) {
                unsigned b[2];
                const float* bb = Ks + (nt * 8 + grp) * FSTR + ko + tig;
                b[0] = __float_as_uint(bb[0]);
                b[1] = __float_as_uint(bb[4]);
                mma_tf32(sacc[nt], a, b);
            }
        }

        // Causal mask + row max
        float rmax0 = -1e30f, rmax1 = -1e30f;
#pragma unroll
        for (int nt = 0; nt < 8; nt++) {
            int c0 = kbase + nt * 8 + 2 * tig;
            int c1 = c0 + 1;
            if (c0 > rowg0) sacc[nt][0] = -1e30f;
            if (c1 > rowg0) sacc[nt][1] = -1e30f;
            if (c0 > rowg1) sacc[nt][2] = -1e30f;
            if (c1 > rowg1) sacc[nt][3] = -1e30f;
            rmax0 = fmaxf(rmax0, fmaxf(sacc[nt][0], sacc[nt][1]));
            rmax1 = fmaxf(rmax1, fmaxf(sacc[nt][2], sacc[nt][3]));
        }
#pragma unroll
        for (int off = 1; off <= 2; off <<= 1) {
            rmax0 = fmaxf(rmax0, __shfl_xor_sync(0xFFFFFFFFu, rmax0, off));
            rmax1 = fmaxf(rmax1, __shfl_xor_sync(0xFFFFFFFFu, rmax1, off));
        }

        float mn0 = fmaxf(m0s, rmax0);
        float mn1 = fmaxf(m1s, rmax1);
        float alpha0 = __expf(m0s - mn0);
        float alpha1 = __expf(m1s - mn1);
        m0s = mn0; m1s = mn1;

        float psum0 = 0.0f, psum1 = 0.0f;
        float* prow0 = Ps + (m0 + grp) * PSTR2;
        float* prow1 = prow0 + 8 * PSTR2;
#pragma unroll
        for (int nt = 0; nt < 8; nt++) {
            float p0 = __expf(sacc[nt][0] - mn0);
            float p1 = __expf(sacc[nt][1] - mn0);
            float p2 = __expf(sacc[nt][2] - mn1);
            float p3 = __expf(sacc[nt][3] - mn1);
            psum0 += p0 + p1;
            psum1 += p2 + p3;
            *(float2*)(prow0 + nt * 8 + 2 * tig) = make_float2(tf32f(p0), tf32f(p1));
            *(float2*)(prow1 + nt * 8 + 2 * tig) = make_float2(tf32f(p2), tf32f(p3));
        }
#pragma unroll
        for (int off = 1; off <= 2; off <<= 1) {
            psum0 += __shfl_xor_sync(0xFFFFFFFFu, psum0, off);
            psum1 += __shfl_xor_sync(0xFFFFFFFFu, psum1, off);
        }
        l0 = l0 * alpha0 + psum0;
        l1 = l1 * alpha1 + psum1;

#pragma unroll
        for (int nt = 0; nt < 16; nt++) {
            o[nt][0] *= alpha0; o[nt][1] *= alpha0;
            o[nt][2] *= alpha1; o[nt][3] *= alpha1;
        }
        __syncwarp();

        // O += P V : warp 16 x 128 (16 n-tiles), K-loop over BK=64
#pragma unroll
        for (int k8 = 0; k8 < 8; k8++) {
            const int ko = k8 * 8;
            unsigned a[4];
            const float* ab = Ps + (m0 + grp) * PSTR2 + ko + tig;
            a[0] = __float_as_uint(ab[0]);
            a[1] = __float_as_uint(ab[8 * PSTR2]);
            a[2] = __float_as_uint(ab[4]);
            a[3] = __float_as_uint(ab[8 * PSTR2 + 4]);
#pragma unroll
            for (int nt = 0; nt < 16; nt++) {
                unsigned b[2];
                b[0] = __float_as_uint(Vs[(ko + tig) * FSTR + nt * 8 + grp]);
                b[1] = __float_as_uint(Vs[(ko + tig + 4) * FSTR + nt * 8 + grp]);
                mma_tf32(o[nt], a, b);
            }
        }
    }

    // Epilogue
    float inv0 = 1.0f / l0;
    float inv1 = 1.0f / l1;
    float* y0 = Y + (size_t)rowg0 * DIM + h * HD;
    float* y1 = Y + (size_t)rowg1 * DIM + h * HD;
#pragma unroll
    for (int nt = 0; nt < 16; nt++) {
        *(float2*)(y0 + nt * 8 + 2 * tig) = make_float2(o[nt][0] * inv0, o[nt][1] * inv0);
        *(float2*)(y1 + nt * 8 + 2 * tig) = make_float2(o[nt][2] * inv1, o[nt][3] * inv1);
    }
}

// ---------------------------------------------------------------------------
// Launch
// ---------------------------------------------------------------------------
extern "C" void kernel_launch(void* const* d_in, const int* in_sizes, int n_in,
                              void* d_out, int out_size) {
    const float* x  = (const float*)d_in[0];
    const float* wq = (const float*)d_in[1];
    const float* wk = (const float*)d_in[2];
    const float* wv = (const float*)d_in[3];
    const float* wo = (const float*)d_in[4];
    const float* fc = (const float*)d_in[5];
    const float* fs = (const float*)d_in[6];
    float* out = (float*)d_out;

    float *q, *k, *v, *y;
    cudaGetSymbolAddress((void**)&q, g_q);
    cudaGetSymbolAddress((void**)&k, g_k);
    cudaGetSymbolAddress((void**)&v, g_v);
    cudaGetSymbolAddress((void**)&y, g_y);

    cudaFuncSetAttribute(gemm_tf32_kernel, cudaFuncAttributeMaxDynamicSharedMemorySize,
                         GEMM_SMEM);
    cudaFuncSetAttribute(flash_tc_kernel, cudaFuncAttributeMaxDynamicSharedMemorySize,
                         FLASH_SMEM);

    gemm_tf32_kernel<<<dim3(DIM / 128, SEQ / 128), 256, GEMM_SMEM>>>(x, wq, q, SEQ, DIM, DIM);
    gemm_tf32_kernel<<<dim3(KVDIM / 128, SEQ / 128), 256, GEMM_SMEM>>>(x, wk, k, SEQ, KVDIM, DIM);
    gemm_tf32_kernel<<<dim3(KVDIM / 128, SEQ / 128), 256, GEMM_SMEM>>>(x, wv, v, SEQ, KVDIM, DIM);

    int tot = SEQ * (NH + NKV) * (HD / 2);
    rope_kernel<<<(tot + 255) / 256, 256>>>(q, k, fc, fs);

    flash_tc_kernel<<<dim3(SEQ / BQ, NH), 256, FLASH_SMEM>>>(q, k, v, y);

    gemm_tf32_kernel<<<dim3(DIM / 128, SEQ / 128), 256, GEMM_SMEM>>>(y, wo, out, SEQ, DIM, DIM);
}

// round 8
// speedup vs baseline: 2.9132x; 1.0088x over previous
#include <cuda_runtime.h>
#include <math.h>
#include <stdint.h>

#define SEQ   2048
#define DIM   4096
#define NH    32
#define NKV   8
#define HD    128
#define KVDIM (NKV * HD)   // 1024

// Scratch (device globals: allocation-free rule)
__device__ float g_q[SEQ * DIM];
__device__ float g_k[SEQ * KVDIM];
__device__ float g_v[SEQ * KVDIM];
__device__ float g_y[SEQ * DIM];
// tf32-pre-rounded operand copies
__device__ float g_x[SEQ * DIM];
__device__ float g_wq[DIM * DIM];
__device__ float g_wk[KVDIM * DIM];
__device__ float g_wv[KVDIM * DIM];
__device__ float g_wo[DIM * DIM];

__device__ __forceinline__ unsigned f2tf32(float x) {
    unsigned r;
    asm("cvt.rna.tf32.f32 %0, %1;" : "=r"(r) : "f"(x));
    return r;
}
__device__ __forceinline__ float tf32f(float x) {
    return __uint_as_float(f2tf32(x));
}
__device__ __forceinline__ void cp16(void* smem_dst, const void* gsrc) {
    unsigned d = (unsigned)__cvta_generic_to_shared(smem_dst);
    asm volatile("cp.async.cg.shared.global [%0], [%1], 16;" :: "r"(d), "l"(gsrc));
}
__device__ __forceinline__ void mma_tf32(float c[4], const unsigned a[4], const unsigned b[2]) {
    asm volatile(
        "mma.sync.aligned.m16n8k8.row.col.f32.tf32.tf32.f32 "
        "{%0,%1,%2,%3}, {%4,%5,%6,%7}, {%8,%9}, {%0,%1,%2,%3};"
        : "+f"(c[0]), "+f"(c[1]), "+f"(c[2]), "+f"(c[3])
        : "r"(a[0]), "r"(a[1]), "r"(a[2]), "r"(a[3]), "r"(b[0]), "r"(b[1]));
}

// ---------------------------------------------------------------------------
// tf32 rounding prepass: out[i] = tf32(in[i])   (float4 granularity)
// ---------------------------------------------------------------------------
__global__ void cvt_tf32_kernel(const float* __restrict__ in, float* __restrict__ out,
                                int n4) {
    int i = blockIdx.x * blockDim.x + threadIdx.x;
    if (i >= n4) return;
    float4 v = ((const float4*)in)[i];
    ((float4*)out)[i] = make_float4(tf32f(v.x), tf32f(v.y), tf32f(v.z), tf32f(v.w));
}

// ---------------------------------------------------------------------------
// TF32 GEMM (NT): C[M,N] = A[M,K] * B[N,K]^T.  Operands MUST be pre-rounded
// to tf32. 128x128 tile, BK=32, 256 thr, cp.async 2-stage double buffer.
// Inner loop: pure LDS + HMMA (no cvt).
// ---------------------------------------------------------------------------
#define GSTR 36
#define GEMM_SMEM (2 * 2 * 128 * GSTR * 4)   // 73728 B

__global__ __launch_bounds__(256, 2)
void gemm_tf32_kernel(const float* __restrict__ A, const float* __restrict__ B,
                      float* __restrict__ C, int M, int N, int K) {
    extern __shared__ float gsm[];
    float* As = gsm;                    // [2][128*GSTR]
    float* Bs = gsm + 2 * 128 * GSTR;   // [2][128*GSTR]

    const int tid  = threadIdx.x;
    const int lane = tid & 31;
    const int wid  = tid >> 5;
    const int grp  = lane >> 2;
    const int tig  = lane & 3;

    const int bm = blockIdx.y * 128;
    const int bn = blockIdx.x * 128;
    const int wm = (wid & 1) * 64;
    const int wn = (wid >> 1) * 32;

    const int lrow = tid >> 1;
    const int lcb  = (tid & 1) * 16;

    const float* Ap = A + (size_t)(bm + lrow) * K + lcb;
    const float* Bp = B + (size_t)(bn + lrow) * K + lcb;

    float acc[4][4][4];
#pragma unroll
    for (int i = 0; i < 4; i++)
#pragma unroll
        for (int j = 0; j < 4; j++)
#pragma unroll
            for (int t = 0; t < 4; t++) acc[i][j][t] = 0.0f;

    const int nk = K / 32;

    // prologue: stage 0
#pragma unroll
    for (int q4 = 0; q4 < 4; q4++) {
        cp16(As + lrow * GSTR + lcb + q4 * 4, Ap + q4 * 4);
        cp16(Bs + lrow * GSTR + lcb + q4 * 4, Bp + q4 * 4);
    }
    asm volatile("cp.async.commit_group;");

    for (int t = 0; t < nk; t++) {
        if (t + 1 < nk) {
            int buf = (t + 1) & 1;
            const float* Apn = Ap + (t + 1) * 32;
            const float* Bpn = Bp + (t + 1) * 32;
#pragma unroll
            for (int q4 = 0; q4 < 4; q4++) {
                cp16(As + buf * 128 * GSTR + lrow * GSTR + lcb + q4 * 4, Apn + q4 * 4);
                cp16(Bs + buf * 128 * GSTR + lrow * GSTR + lcb + q4 * 4, Bpn + q4 * 4);
            }
            asm volatile("cp.async.commit_group;");
            asm volatile("cp.async.wait_group 1;");
        } else {
            asm volatile("cp.async.wait_group 0;");
        }
        __syncthreads();

        const float* Ab = As + (t & 1) * 128 * GSTR;
        const float* Bb = Bs + (t & 1) * 128 * GSTR;
#pragma unroll
        for (int kk = 0; kk < 4; kk++) {
            const int ko = kk * 8;
            unsigned af[4][4], bf[4][2];
#pragma unroll
            for (int i = 0; i < 4; i++) {
                const float* base = Ab + (wm + i * 16 + grp) * GSTR + ko + tig;
                af[i][0] = __float_as_uint(base[0]);
                af[i][1] = __float_as_uint(base[8 * GSTR]);
                af[i][2] = __float_as_uint(base[4]);
                af[i][3] = __float_as_uint(base[8 * GSTR + 4]);
            }
#pragma unroll
            for (int j = 0; j < 4; j++) {
                const float* base = Bb + (wn + j * 8 + grp) * GSTR + ko + tig;
                bf[j][0] = __float_as_uint(base[0]);
                bf[j][1] = __float_as_uint(base[4]);
            }
#pragma unroll
            for (int i = 0; i < 4; i++)
#pragma unroll
                for (int j = 0; j < 4; j++)
                    mma_tf32(acc[i][j], af[i], bf[j]);
        }
        __syncthreads();
    }

#pragma unroll
    for (int i = 0; i < 4; i++)
#pragma unroll
        for (int j = 0; j < 4; j++) {
            int r   = bm + wm + i * 16 + grp;
            int col = bn + wn + j * 8 + tig * 2;
            *(float2*)(C + (size_t)r * N + col) =
                make_float2(acc[i][j][0], acc[i][j][1]);
            *(float2*)(C + (size_t)(r + 8) * N + col) =
                make_float2(acc[i][j][2], acc[i][j][3]);
        }
}

// ---------------------------------------------------------------------------
// RoPE over Q (32 heads) and K (8 heads).
// ---------------------------------------------------------------------------
__global__ void rope_kernel(float* __restrict__ q, float* __restrict__ k,
                            const float* __restrict__ fc, const float* __restrict__ fs) {
    const int PAIRS = HD / 2;
    int idx = blockIdx.x * blockDim.x + threadIdx.x;
    const int TOT = SEQ * (NH + NKV) * PAIRS;
    if (idx >= TOT) return;
    int p = idx % PAIRS;
    int h = (idx / PAIRS) % (NH + NKV);
    int s = idx / (PAIRS * (NH + NKV));
    float c  = fc[s * PAIRS + p];
    float sn = fs[s * PAIRS + p];
    float* base;
    if (h < NH) base = q + (size_t)s * DIM + h * HD + 2 * p;
    else        base = k + (size_t)s * KVDIM + (h - NH) * HD + 2 * p;
    float2 ri = *(float2*)base;
    float2 outv;
    outv.x = ri.x * c - ri.y * sn;
    outv.y = ri.x * sn + ri.y * c;
    *(float2*)base = outv;
}

// ---------------------------------------------------------------------------
// Tensor-core flash attention (causal, GQA) — mma tf32.
// Epilogue writes tf32-rounded y so the WO GEMM needs no cvt.
// ---------------------------------------------------------------------------
#define BQ    128
#define BK    64
#define FSTR  136
#define PSTR2 72
#define FLASH_SMEM ((BQ * FSTR + 2 * BK * FSTR + BQ * PSTR2) * 4)

__global__ __launch_bounds__(256, 1)
void flash_tc_kernel(const float* __restrict__ Q, const float* __restrict__ K,
                     const float* __restrict__ V, float* __restrict__ Y) {
    extern __shared__ float sm[];
    float* Qs = sm;
    float* Ks = Qs + BQ * FSTR;
    float* Vs = Ks + BK * FSTR;
    float* Ps = Vs + BK * FSTR;

    const int tid  = threadIdx.x;
    const int lane = tid & 31;
    const int w    = tid >> 5;
    const int grp  = lane >> 2;
    const int tig  = lane & 3;
    const int h    = blockIdx.y;
    const int kh   = h >> 2;
    const int qbase = blockIdx.x * BQ;
    const int m0   = w * 16;
    const float scale = 0.08838834764831845f;

#pragma unroll
    for (int i = 0; i < 16; i++) {
        int lin = tid + i * 256;
        int row = lin >> 5;
        int c4  = (lin & 31) << 2;
        float4 v = *(const float4*)(Q + (size_t)(qbase + row) * DIM + h * HD + c4);
        float* dst = Qs + row * FSTR + c4;
        dst[0] = tf32f(v.x * scale); dst[1] = tf32f(v.y * scale);
        dst[2] = tf32f(v.z * scale); dst[3] = tf32f(v.w * scale);
    }

    float m0s = -1e30f, m1s = -1e30f, l0 = 0.0f, l1 = 0.0f;
    float o[16][4];
#pragma unroll
    for (int nt = 0; nt < 16; nt++)
#pragma unroll
        for (int t = 0; t < 4; t++) o[nt][t] = 0.0f;

    const int rowg0 = qbase + m0 + grp;
    const int rowg1 = rowg0 + 8;
    const int ntiles = (qbase + BQ) / BK;

    for (int kt = 0; kt < ntiles; kt++) {
        const int kbase = kt * BK;
        __syncthreads();

#pragma unroll
        for (int i = 0; i < 8; i++) {
            int lin = tid + i * 256;
            int row = lin >> 5;
            int c4  = (lin & 31) << 2;
            float4 kv = *(const float4*)(K + (size_t)(kbase + row) * KVDIM + kh * HD + c4);
            float4 vv = *(const float4*)(V + (size_t)(kbase + row) * KVDIM + kh * HD + c4);
            float* kd = Ks + row * FSTR + c4;
            float* vd = Vs + row * FSTR + c4;
            kd[0] = tf32f(kv.x); kd[1] = tf32f(kv.y);
            kd[2] = tf32f(kv.z); kd[3] = tf32f(kv.w);
            vd[0] = tf32f(vv.x); vd[1] = tf32f(vv.y);
            vd[2] = tf32f(vv.z); vd[3] = tf32f(vv.w);
        }
        __syncthreads();

        float sacc[8][4];
#pragma unroll
        for (int nt = 0; nt < 8; nt++)
#pragma unroll
            for (int t = 0; t < 4; t++) sacc[nt][t] = 0.0f;

#pragma unroll
        for (int k8 = 0; k8 < 16; k8++) {
            const int ko = k8 * 8;
            unsigned a[4];
            const float* ab = Qs + (m0 + grp) * FSTR + ko + tig;
            a[0] = __float_as_uint(ab[0]);
            a[1] = __float_as_uint(ab[8 * FSTR]);
            a[2] = __float_as_uint(ab[4]);
            a[3] = __float_as_uint(ab[8 * FSTR + 4]);
#pragma unroll
            for (int nt = 0; nt < 8; nt++) {
                unsigned b[2];
                const float* bb = Ks + (nt * 8 + grp) * FSTR + ko + tig;
                b[0] = __float_as_uint(bb[0]);
                b[1] = __float_as_uint(bb[4]);
                mma_tf32(sacc[nt], a, b);
            }
        }

        float rmax0 = -1e30f, rmax1 = -1e30f;
#pragma unroll
        for (int nt = 0; nt < 8; nt++) {
            int c0 = kbase + nt * 8 + 2 * tig;
            int c1 = c0 + 1;
            if (c0 > rowg0) sacc[nt][0] = -1e30f;
            if (c1 > rowg0) sacc[nt][1] = -1e30f;
            if (c0 > rowg1) sacc[nt][2] = -1e30f;
            if (c1 > rowg1) sacc[nt][3] = -1e30f;
            rmax0 = fmaxf(rmax0, fmaxf(sacc[nt][0], sacc[nt][1]));
            rmax1 = fmaxf(rmax1, fmaxf(sacc[nt][2], sacc[nt][3]));
        }
#pragma unroll
        for (int off = 1; off <= 2; off <<= 1) {
            rmax0 = fmaxf(rmax0, __shfl_xor_sync(0xFFFFFFFFu, rmax0, off));
            rmax1 = fmaxf(rmax1, __shfl_xor_sync(0xFFFFFFFFu, rmax1, off));
        }

        float mn0 = fmaxf(m0s, rmax0);
        float mn1 = fmaxf(m1s, rmax1);
        float alpha0 = __expf(m0s - mn0);
        float alpha1 = __expf(m1s - mn1);
        m0s = mn0; m1s = mn1;

        float psum0 = 0.0f, psum1 = 0.0f;
        float* prow0 = Ps + (m0 + grp) * PSTR2;
        float* prow1 = prow0 + 8 * PSTR2;
#pragma unroll
        for (int nt = 0; nt < 8; nt++) {
            float p0 = __expf(sacc[nt][0] - mn0);
            float p1 = __expf(sacc[nt][1] - mn0);
            float p2 = __expf(sacc[nt][2] - mn1);
            float p3 = __expf(sacc[nt][3] - mn1);
            psum0 += p0 + p1;
            psum1 += p2 + p3;
            *(float2*)(prow0 + nt * 8 + 2 * tig) = make_float2(tf32f(p0), tf32f(p1));
            *(float2*)(prow1 + nt * 8 + 2 * tig) = make_float2(tf32f(p2), tf32f(p3));
        }
#pragma unroll
        for (int off = 1; off <= 2; off <<= 1) {
            psum0 += __shfl_xor_sync(0xFFFFFFFFu, psum0, off);
            psum1 += __shfl_xor_sync(0xFFFFFFFFu, psum1, off);
        }
        l0 = l0 * alpha0 + psum0;
        l1 = l1 * alpha1 + psum1;

#pragma unroll
        for (int nt = 0; nt < 16; nt++) {
            o[nt][0] *= alpha0; o[nt][1] *= alpha0;
            o[nt][2] *= alpha1; o[nt][3] *= alpha1;
        }
        __syncwarp();

#pragma unroll
        for (int k8 = 0; k8 < 8; k8++) {
            const int ko = k8 * 8;
            unsigned a[4];
            const float* ab = Ps + (m0 + grp) * PSTR2 + ko + tig;
            a[0] = __float_as_uint(ab[0]);
            a[1] = __float_as_uint(ab[8 * PSTR2]);
            a[2] = __float_as_uint(ab[4]);
            a[3] = __float_as_uint(ab[8 * PSTR2 + 4]);
#pragma unroll
            for (int nt = 0; nt < 16; nt++) {
                unsigned b[2];
                b[0] = __float_as_uint(Vs[(ko + tig) * FSTR + nt * 8 + grp]);
                b[1] = __float_as_uint(Vs[(ko + tig + 4) * FSTR + nt * 8 + grp]);
                mma_tf32(o[nt], a, b);
            }
        }
    }

    // Epilogue: tf32-rounded so WO GEMM can consume raw bits
    float inv0 = 1.0f / l0;
    float inv1 = 1.0f / l1;
    float* y0 = Y + (size_t)rowg0 * DIM + h * HD;
    float* y1 = Y + (size_t)rowg1 * DIM + h * HD;
#pragma unroll
    for (int nt = 0; nt < 16; nt++) {
        *(float2*)(y0 + nt * 8 + 2 * tig) =
            make_float2(tf32f(o[nt][0] * inv0), tf32f(o[nt][1] * inv0));
        *(float2*)(y1 + nt * 8 + 2 * tig) =
            make_float2(tf32f(o[nt][2] * inv1), tf32f(o[nt][3] * inv1));
    }
}

// ---------------------------------------------------------------------------
// Launch
// ---------------------------------------------------------------------------
extern "C" void kernel_launch(void* const* d_in, const int* in_sizes, int n_in,
                              void* d_out, int out_size) {
    const float* x  = (const float*)d_in[0];
    const float* wq = (const float*)d_in[1];
    const float* wk = (const float*)d_in[2];
    const float* wv = (const float*)d_in[3];
    const float* wo = (const float*)d_in[4];
    const float* fc = (const float*)d_in[5];
    const float* fs = (const float*)d_in[6];
    float* out = (float*)d_out;

    float *q, *k, *v, *y, *xc, *wqc, *wkc, *wvc, *woc;
    cudaGetSymbolAddress((void**)&q, g_q);
    cudaGetSymbolAddress((void**)&k, g_k);
    cudaGetSymbolAddress((void**)&v, g_v);
    cudaGetSymbolAddress((void**)&y, g_y);
    cudaGetSymbolAddress((void**)&xc, g_x);
    cudaGetSymbolAddress((void**)&wqc, g_wq);
    cudaGetSymbolAddress((void**)&wkc, g_wk);
    cudaGetSymbolAddress((void**)&wvc, g_wv);
    cudaGetSymbolAddress((void**)&woc, g_wo);

    cudaFuncSetAttribute(gemm_tf32_kernel, cudaFuncAttributeMaxDynamicSharedMemorySize,
                         GEMM_SMEM);
    cudaFuncSetAttribute(flash_tc_kernel, cudaFuncAttributeMaxDynamicSharedMemorySize,
                         FLASH_SMEM);

    // tf32 rounding prepass (idempotent elementwise copies)
    {
        int n4;
        n4 = SEQ * DIM / 4;
        cvt_tf32_kernel<<<(n4 + 255) / 256, 256>>>(x, xc, n4);
        n4 = DIM * DIM / 4;
        cvt_tf32_kernel<<<(n4 + 255) / 256, 256>>>(wq, wqc, n4);
        n4 = KVDIM * DIM / 4;
        cvt_tf32_kernel<<<(n4 + 255) / 256, 256>>>(wk, wkc, n4);
        cvt_tf32_kernel<<<(n4 + 255) / 256, 256>>>(wv, wvc, n4);
        n4 = DIM * DIM / 4;
        cvt_tf32_kernel<<<(n4 + 255) / 256, 256>>>(wo, woc, n4);
    }

    gemm_tf32_kernel<<<dim3(DIM / 128, SEQ / 128), 256, GEMM_SMEM>>>(xc, wqc, q, SEQ, DIM, DIM);
    gemm_tf32_kernel<<<dim3(KVDIM / 128, SEQ / 128), 256, GEMM_SMEM>>>(xc, wkc, k, SEQ, KVDIM, DIM);
    gemm_tf32_kernel<<<dim3(KVDIM / 128, SEQ / 128), 256, GEMM_SMEM>>>(xc, wvc, v, SEQ, KVDIM, DIM);

    int tot = SEQ * (NH + NKV) * (HD / 2);
    rope_kernel<<<(tot + 255) / 256, 256>>>(q, k, fc, fs);

    flash_tc_kernel<<<dim3(SEQ / BQ, NH), 256, FLASH_SMEM>>>(q, k, v, y);

    gemm_tf32_kernel<<<dim3(DIM / 128, SEQ / 128), 256, GEMM_SMEM>>>(y, woc, out, SEQ, DIM, DIM);
}

// round 10
// speedup vs baseline: 6.5223x; 2.2389x over previous
#include <cuda_runtime.h>
#include <cuda_fp16.h>
#include <math.h>
#include <stdint.h>

#define SEQ   2048
#define DIM   4096
#define NH    32
#define NKV   8
#define HD    128
#define KVDIM (NKV * HD)   // 1024

// Scratch (device globals: allocation-free rule)
__device__ float  g_q[SEQ * DIM];
__device__ float  g_k[SEQ * KVDIM];
__device__ float  g_v[SEQ * KVDIM];
__device__ __half g_yh[SEQ * DIM];
__device__ __half g_xh[SEQ * DIM];
__device__ __half g_wqh[DIM * DIM];
__device__ __half g_wkh[KVDIM * DIM];
__device__ __half g_wvh[KVDIM * DIM];
__device__ __half g_woh[DIM * DIM];
__device__ __half g_vth[KVDIM * SEQ];   // V transposed: [kvdim][seq]

// ---------------------------------------------------------------------------
// Helpers
// ---------------------------------------------------------------------------
__device__ __forceinline__ unsigned h2u(__half2 h) { return *(unsigned*)&h; }

__device__ __forceinline__ void cp16(void* smem_dst, const void* gsrc) {
    unsigned d = (unsigned)__cvta_generic_to_shared(smem_dst);
    asm volatile("cp.async.cg.shared.global [%0], [%1], 16;" :: "r"(d), "l"(gsrc));
}
__device__ __forceinline__ void mma_f16(float c[4], const unsigned a[4], const unsigned b[2]) {
    asm volatile(
        "mma.sync.aligned.m16n8k16.row.col.f32.f16.f16.f32 "
        "{%0,%1,%2,%3}, {%4,%5,%6,%7}, {%8,%9}, {%0,%1,%2,%3};"
        : "+f"(c[0]), "+f"(c[1]), "+f"(c[2]), "+f"(c[3])
        : "r"(a[0]), "r"(a[1]), "r"(a[2]), "r"(a[3]), "r"(b[0]), "r"(b[1]));
}

// fp32 -> fp16 conversion prepass (float4 -> 4 halves)
__global__ void cvt_h_kernel(const float* __restrict__ in, __half* __restrict__ out,
                             int n4) {
    int i = blockIdx.x * blockDim.x + threadIdx.x;
    if (i >= n4) return;
    float4 v = ((const float4*)in)[i];
    __half2 h0 = __floats2half2_rn(v.x, v.y);
    __half2 h1 = __floats2half2_rn(v.z, v.w);
    ((uint2*)out)[i] = make_uint2(h2u(h0), h2u(h1));
}

// V transpose: v[seq][kvdim] fp32 -> vt[kvdim][seq] fp16
__global__ void transpose_v_kernel(const float* __restrict__ v, __half* __restrict__ vt) {
    __shared__ float t[32][33];
    int s0 = blockIdx.x * 32;
    int d0 = blockIdx.y * 32;
    int x = threadIdx.x, y = threadIdx.y;   // 32 x 8
#pragma unroll
    for (int j = 0; j < 32; j += 8)
        t[y + j][x] = v[(size_t)(s0 + y + j) * KVDIM + d0 + x];
    __syncthreads();
#pragma unroll
    for (int j = 0; j < 32; j += 8)
        vt[(size_t)(d0 + y + j) * SEQ + s0 + x] = __float2half(t[x][y + j]);
}

// ---------------------------------------------------------------------------
// FP16 GEMM (NT): C[M,N] = A[M,K] * B[N,K]^T, fp16 in / fp32 out.
// 128x128 tile, BK=32, 256 thr, 8 warps x (64x32), cp.async double buffer.
// ---------------------------------------------------------------------------
#define GSH 56   // smem row stride in halves (112B: 16B-aligned, conflict-free)
#define GEMM_SMEM (2 * 2 * 128 * GSH * 2)   // 57344 B

__global__ __launch_bounds__(256, 2)
void gemm_f16_kernel(const __half* __restrict__ A, const __half* __restrict__ B,
                     float* __restrict__ C, int M, int N, int K) {
    extern __shared__ __half hsm[];
    __half* As = hsm;                    // [2][128*GSH]
    __half* Bs = hsm + 2 * 128 * GSH;

    const int tid  = threadIdx.x;
    const int lane = tid & 31;
    const int wid  = tid >> 5;
    const int grp  = lane >> 2;
    const int tig  = lane & 3;

    const int bm = blockIdx.y * 128;
    const int bn = blockIdx.x * 128;
    const int wm = (wid & 1) * 64;
    const int wn = (wid >> 1) * 32;

    float acc[4][4][4];
#pragma unroll
    for (int i = 0; i < 4; i++)
#pragma unroll
        for (int j = 0; j < 4; j++)
#pragma unroll
            for (int t = 0; t < 4; t++) acc[i][j][t] = 0.0f;

    const int nk = K / 32;

    // loader: 128 rows x 32 halves = 512 16B-chunks per matrix; 2 per thread
    auto load_stage = [&](int t, int buf) {
        const int koff = t * 32;
        __half* Ad = As + buf * 128 * GSH;
        __half* Bd = Bs + buf * 128 * GSH;
#pragma unroll
        for (int u = 0; u < 2; u++) {
            int id  = tid + u * 256;
            int row = id >> 2;
            int o8  = (id & 3) * 8;
            cp16(Ad + row * GSH + o8, A + (size_t)(bm + row) * K + koff + o8);
            cp16(Bd + row * GSH + o8, B + (size_t)(bn + row) * K + koff + o8);
        }
    };

    load_stage(0, 0);
    asm volatile("cp.async.commit_group;");

    for (int t = 0; t < nk; t++) {
        if (t + 1 < nk) {
            load_stage(t + 1, (t + 1) & 1);
            asm volatile("cp.async.commit_group;");
            asm volatile("cp.async.wait_group 1;");
        } else {
            asm volatile("cp.async.wait_group 0;");
        }
        __syncthreads();

        const __half* Ab = As + (t & 1) * 128 * GSH;
        const __half* Bb = Bs + (t & 1) * 128 * GSH;
#pragma unroll
        for (int kk = 0; kk < 2; kk++) {      // two k16 steps per BK=32
            const int ko = kk * 16;
            unsigned af[4][4], bf[4][2];
#pragma unroll
            for (int i = 0; i < 4; i++) {
                const __half* base = Ab + (wm + i * 16 + grp) * GSH + ko + 2 * tig;
                af[i][0] = *(const unsigned*)(base);
                af[i][1] = *(const unsigned*)(base + 8 * GSH);
                af[i][2] = *(const unsigned*)(base + 8);
                af[i][3] = *(const unsigned*)(base + 8 * GSH + 8);
            }
#pragma unroll
            for (int j = 0; j < 4; j++) {
                const __half* base = Bb + (wn + j * 8 + grp) * GSH + ko + 2 * tig;
                bf[j][0] = *(const unsigned*)(base);
                bf[j][1] = *(const unsigned*)(base + 8);
            }
#pragma unroll
            for (int i = 0; i < 4; i++)
#pragma unroll
                for (int j = 0; j < 4; j++)
                    mma_f16(acc[i][j], af[i], bf[j]);
        }
        __syncthreads();
    }

#pragma unroll
    for (int i = 0; i < 4; i++)
#pragma unroll
        for (int j = 0; j < 4; j++) {
            int r   = bm + wm + i * 16 + grp;
            int col = bn + wn + j * 8 + tig * 2;
            *(float2*)(C + (size_t)r * N + col) =
                make_float2(acc[i][j][0], acc[i][j][1]);
            *(float2*)(C + (size_t)(r + 8) * N + col) =
                make_float2(acc[i][j][2], acc[i][j][3]);
        }
}

// ---------------------------------------------------------------------------
// RoPE over Q (32 heads) and K (8 heads), fp32 in-place.
// ---------------------------------------------------------------------------
__global__ void rope_kernel(float* __restrict__ q, float* __restrict__ k,
                            const float* __restrict__ fc, const float* __restrict__ fs) {
    const int PAIRS = HD / 2;
    int idx = blockIdx.x * blockDim.x + threadIdx.x;
    const int TOT = SEQ * (NH + NKV) * PAIRS;
    if (idx >= TOT) return;
    int p = idx % PAIRS;
    int h = (idx / PAIRS) % (NH + NKV);
    int s = idx / (PAIRS * (NH + NKV));
    float c  = fc[s * PAIRS + p];
    float sn = fs[s * PAIRS + p];
    float* base;
    if (h < NH) base = q + (size_t)s * DIM + h * HD + 2 * p;
    else        base = k + (size_t)s * KVDIM + (h - NH) * HD + 2 * p;
    float2 ri = *(float2*)base;
    float2 outv;
    outv.x = ri.x * c - ri.y * sn;
    outv.y = ri.x * sn + ri.y * c;
    *(float2*)base = outv;
}

// ---------------------------------------------------------------------------
// FP16 tensor-core flash attention (causal, GQA).
// Block = 128 q-rows x 1 head, 256 thr = 8 warps, warp owns 16 q-rows.
// S = Q K^T (mma f16, fp32 acc), online softmax fp32, P->smem half,
// O += P V via mma f16 with V pre-transposed (d-major).
// ---------------------------------------------------------------------------
#define BQ   128
#define BK   64
#define FSH  136   // Qs/Ks row stride (halves)
#define VSH  72    // Vst/Ps row stride (halves)
#define FLASH_SMEM ((BQ * FSH + BK * FSH + HD * VSH + BQ * VSH) * 2)

__global__ __launch_bounds__(256, 1)
void flash_f16_kernel(const float* __restrict__ Q, const float* __restrict__ K,
                      const __half* __restrict__ VT, __half* __restrict__ Y) {
    extern __shared__ __half fsm[];
    __half* Qs  = fsm;                    // 128 x FSH
    __half* Ks  = Qs + BQ * FSH;          // 64 x FSH
    __half* Vst = Ks + BK * FSH;          // 128(d) x VSH
    __half* Ps  = Vst + HD * VSH;         // 128 x VSH

    const int tid  = threadIdx.x;
    const int lane = tid & 31;
    const int w    = tid >> 5;
    const int grp  = lane >> 2;
    const int tig  = lane & 3;
    const int h    = blockIdx.y;
    const int kh   = h >> 2;
    const int qbase = blockIdx.x * BQ;
    const int m0   = w * 16;
    const float scale = 0.08838834764831845f;

    // Load Q tile (pre-scaled fp32 -> half)
#pragma unroll
    for (int i = 0; i < 16; i++) {
        int lin = tid + i * 256;
        int row = lin >> 5;
        int c4  = (lin & 31) << 2;
        float4 v = *(const float4*)(Q + (size_t)(qbase + row) * DIM + h * HD + c4);
        __half2 h0 = __floats2half2_rn(v.x * scale, v.y * scale);
        __half2 h1 = __floats2half2_rn(v.z * scale, v.w * scale);
        *(uint2*)(Qs + row * FSH + c4) = make_uint2(h2u(h0), h2u(h1));
    }

    float m0s = -1e30f, m1s = -1e30f, l0 = 0.0f, l1 = 0.0f;
    float o[16][4];
#pragma unroll
    for (int nt = 0; nt < 16; nt++)
#pragma unroll
        for (int t = 0; t < 4; t++) o[nt][t] = 0.0f;

    const int rowg0 = qbase + m0 + grp;
    const int rowg1 = rowg0 + 8;
    const int ntiles = (qbase + BQ) / BK;

    for (int kt = 0; kt < ntiles; kt++) {
        const int kbase = kt * BK;
        __syncthreads();

        // K tile: 64x128 fp32 -> half (8 float4 per thread)
#pragma unroll
        for (int i = 0; i < 8; i++) {
            int lin = tid + i * 256;
            int row = lin >> 5;
            int c4  = (lin & 31) << 2;
            float4 kv = *(const float4*)(K + (size_t)(kbase + row) * KVDIM + kh * HD + c4);
            __half2 h0 = __floats2half2_rn(kv.x, kv.y);
            __half2 h1 = __floats2half2_rn(kv.z, kv.w);
            *(uint2*)(Ks + row * FSH + c4) = make_uint2(h2u(h0), h2u(h1));
        }
        // V tile (transposed, already half): 128 d-rows x 64 k-halves (4 uint4/thread)
#pragma unroll
        for (int i = 0; i < 4; i++) {
            int id  = tid + i * 256;
            int row = id >> 3;
            int c8  = (id & 7) * 8;
            *(uint4*)(Vst + row * VSH + c8) =
                *(const uint4*)(VT + (size_t)(kh * HD + row) * SEQ + kbase + c8);
        }
        __syncthreads();

        // S = Q K^T : 8 k16 steps, 8 n-tiles
        float sacc[8][4];
#pragma unroll
        for (int nt = 0; nt < 8; nt++)
#pragma unroll
            for (int t = 0; t < 4; t++) sacc[nt][t] = 0.0f;

#pragma unroll
        for (int k16 = 0; k16 < 8; k16++) {
            const int ko = k16 * 16;
            unsigned a[4];
            const __half* ab = Qs + (m0 + grp) * FSH + ko + 2 * tig;
            a[0] = *(const unsigned*)(ab);
            a[1] = *(const unsigned*)(ab + 8 * FSH);
            a[2] = *(const unsigned*)(ab + 8);
            a[3] = *(const unsigned*)(ab + 8 * FSH + 8);
#pragma unroll
            for (int nt = 0; nt < 8; nt++) {
                unsigned b[2];
                const __half* bb = Ks + (nt * 8 + grp) * FSH + ko + 2 * tig;
                b[0] = *(const unsigned*)(bb);
                b[1] = *(const unsigned*)(bb + 8);
                mma_f16(sacc[nt], a, b);
            }
        }

        // Causal mask + online softmax (fp32)
        float rmax0 = -1e30f, rmax1 = -1e30f;
#pragma unroll
        for (int nt = 0; nt < 8; nt++) {
            int c0 = kbase + nt * 8 + 2 * tig;
            int c1 = c0 + 1;
            if (c0 > rowg0) sacc[nt][0] = -1e30f;
            if (c1 > rowg0) sacc[nt][1] = -1e30f;
            if (c0 > rowg1) sacc[nt][2] = -1e30f;
            if (c1 > rowg1) sacc[nt][3] = -1e30f;
            rmax0 = fmaxf(rmax0, fmaxf(sacc[nt][0], sacc[nt][1]));
            rmax1 = fmaxf(rmax1, fmaxf(sacc[nt][2], sacc[nt][3]));
        }
#pragma unroll
        for (int off = 1; off <= 2; off <<= 1) {
            rmax0 = fmaxf(rmax0, __shfl_xor_sync(0xFFFFFFFFu, rmax0, off));
            rmax1 = fmaxf(rmax1, __shfl_xor_sync(0xFFFFFFFFu, rmax1, off));
        }

        float mn0 = fmaxf(m0s, rmax0);
        float mn1 = fmaxf(m1s, rmax1);
        float alpha0 = __expf(m0s - mn0);
        float alpha1 = __expf(m1s - mn1);
        m0s = mn0; m1s = mn1;

        float psum0 = 0.0f, psum1 = 0.0f;
        __half* prow0 = Ps + (m0 + grp) * VSH;
        __half* prow1 = prow0 + 8 * VSH;
#pragma unroll
        for (int nt = 0; nt < 8; nt++) {
            float p0 = __expf(sacc[nt][0] - mn0);
            float p1 = __expf(sacc[nt][1] - mn0);
            float p2 = __expf(sacc[nt][2] - mn1);
            float p3 = __expf(sacc[nt][3] - mn1);
            psum0 += p0 + p1;
            psum1 += p2 + p3;
            *(unsigned*)(prow0 + nt * 8 + 2 * tig) = h2u(__floats2half2_rn(p0, p1));
            *(unsigned*)(prow1 + nt * 8 + 2 * tig) = h2u(__floats2half2_rn(p2, p3));
        }
#pragma unroll
        for (int off = 1; off <= 2; off <<= 1) {
            psum0 += __shfl_xor_sync(0xFFFFFFFFu, psum0, off);
            psum1 += __shfl_xor_sync(0xFFFFFFFFu, psum1, off);
        }
        l0 = l0 * alpha0 + psum0;
        l1 = l1 * alpha1 + psum1;

#pragma unroll
        for (int nt = 0; nt < 16; nt++) {
            o[nt][0] *= alpha0; o[nt][1] *= alpha0;
            o[nt][2] *= alpha1; o[nt][3] *= alpha1;
        }
        __syncwarp();

        // O += P V : 4 k16 steps over BK=64, 16 d-tiles
#pragma unroll
        for (int k16 = 0; k16 < 4; k16++) {
            const int ko = k16 * 16;
            unsigned a[4];
            const __half* ab = Ps + (m0 + grp) * VSH + ko + 2 * tig;
            a[0] = *(const unsigned*)(ab);
            a[1] = *(const unsigned*)(ab + 8 * VSH);
            a[2] = *(const unsigned*)(ab + 8);
            a[3] = *(const unsigned*)(ab + 8 * VSH + 8);
#pragma unroll
            for (int nt = 0; nt < 16; nt++) {
                unsigned b[2];
                const __half* bb = Vst + (nt * 8 + grp) * VSH + ko + 2 * tig;
                b[0] = *(const unsigned*)(bb);
                b[1] = *(const unsigned*)(bb + 8);
                mma_f16(o[nt], a, b);
            }
        }
    }

    // Epilogue: normalize, write y as half for WO GEMM
    float inv0 = 1.0f / l0;
    float inv1 = 1.0f / l1;
    __half* y0 = Y + (size_t)rowg0 * DIM + h * HD;
    __half* y1 = Y + (size_t)rowg1 * DIM + h * HD;
#pragma unroll
    for (int nt = 0; nt < 16; nt++) {
        *(unsigned*)(y0 + nt * 8 + 2 * tig) =
            h2u(__floats2half2_rn(o[nt][0] * inv0, o[nt][1] * inv0));
        *(unsigned*)(y1 + nt * 8 + 2 * tig) =
            h2u(__floats2half2_rn(o[nt][2] * inv1, o[nt][3] * inv1));
    }
}

// ---------------------------------------------------------------------------
// Launch
// ---------------------------------------------------------------------------
extern "C" void kernel_launch(void* const* d_in, const int* in_sizes, int n_in,
                              void* d_out, int out_size) {
    const float* x  = (const float*)d_in[0];
    const float* wq = (const float*)d_in[1];
    const float* wk = (const float*)d_in[2];
    const float* wv = (const float*)d_in[3];
    const float* wo = (const float*)d_in[4];
    const float* fc = (const float*)d_in[5];
    const float* fs = (const float*)d_in[6];
    float* out = (float*)d_out;

    float *q, *k, *v;
    __half *yh, *xh, *wqh, *wkh, *wvh, *woh, *vth;
    cudaGetSymbolAddress((void**)&q,   g_q);
    cudaGetSymbolAddress((void**)&k,   g_k);
    cudaGetSymbolAddress((void**)&v,   g_v);
    cudaGetSymbolAddress((void**)&yh,  g_yh);
    cudaGetSymbolAddress((void**)&xh,  g_xh);
    cudaGetSymbolAddress((void**)&wqh, g_wqh);
    cudaGetSymbolAddress((void**)&wkh, g_wkh);
    cudaGetSymbolAddress((void**)&wvh, g_wvh);
    cudaGetSymbolAddress((void**)&woh, g_woh);
    cudaGetSymbolAddress((void**)&vth, g_vth);

    cudaFuncSetAttribute(gemm_f16_kernel, cudaFuncAttributeMaxDynamicSharedMemorySize,
                         GEMM_SMEM);
    cudaFuncSetAttribute(flash_f16_kernel, cudaFuncAttributeMaxDynamicSharedMemorySize,
                         FLASH_SMEM);

    // fp32 -> fp16 prepass
    {
        int n4;
        n4 = SEQ * DIM / 4;
        cvt_h_kernel<<<(n4 + 255) / 256, 256>>>(x, xh, n4);
        n4 = DIM * DIM / 4;
        cvt_h_kernel<<<(n4 + 255) / 256, 256>>>(wq, wqh, n4);
        n4 = KVDIM * DIM / 4;
        cvt_h_kernel<<<(n4 + 255) / 256, 256>>>(wk, wkh, n4);
        cvt_h_kernel<<<(n4 + 255) / 256, 256>>>(wv, wvh, n4);
        n4 = DIM * DIM / 4;
        cvt_h_kernel<<<(n4 + 255) / 256, 256>>>(wo, woh, n4);
    }

    // Projections (fp16 tensor cores, fp32 out)
    gemm_f16_kernel<<<dim3(DIM / 128, SEQ / 128), 256, GEMM_SMEM>>>(xh, wqh, q, SEQ, DIM, DIM);
    gemm_f16_kernel<<<dim3(KVDIM / 128, SEQ / 128), 256, GEMM_SMEM>>>(xh, wkh, k, SEQ, KVDIM, DIM);
    gemm_f16_kernel<<<dim3(KVDIM / 128, SEQ / 128), 256, GEMM_SMEM>>>(xh, wvh, v, SEQ, KVDIM, DIM);

    // RoPE (fp32)
    int tot = SEQ * (NH + NKV) * (HD / 2);
    rope_kernel<<<(tot + 255) / 256, 256>>>(q, k, fc, fs);

    // V transpose (fp32 -> half, d-major)
    transpose_v_kernel<<<dim3(SEQ / 32, KVDIM / 32), dim3(32, 8)>>>(v, vth);

    // Flash attention (fp16 tensor cores)
    flash_f16_kernel<<<dim3(SEQ / BQ, NH), 256, FLASH_SMEM>>>(q, k, vth, yh);

    // Output projection
    gemm_f16_kernel<<<dim3(DIM / 128, SEQ / 128), 256, GEMM_SMEM>>>(yh, woh, out, SEQ, DIM, DIM);
}